// round 3
// baseline (speedup 1.0000x reference)
#include <cuda_runtime.h>
#include <math.h>

#define T_LEN 2048
#define NT 512
#define NW 16            // warps per block
#define FULL 0xFFFFFFFFu

__global__ __launch_bounds__(NT, 4)
void scpp_kernel(const float* __restrict__ event_times,
                 const float* __restrict__ input_mask,
                 const float* __restrict__ t0p,
                 const float* __restrict__ t1p,
                 const float* __restrict__ mup,
                 const float* __restrict__ betap,
                 float* __restrict__ out)
{
    const int row  = blockIdx.x;
    const int tid  = threadIdx.x;
    const int lane = tid & 31;
    const int wid  = tid >> 5;

    const float mu   = log1pf(expf(__ldg(mup)));
    const float beta = log1pf(expf(__ldg(betap)));
    const float t0   = __ldg(t0p);
    const float t1   = __ldg(t1p);

    // ---- perfectly coalesced: one float4 per thread per array ----
    const size_t rbase = (size_t)row * T_LEN;
    const float4 e4 = reinterpret_cast<const float4*>(event_times + rbase)[tid];
    const float4 m4 = reinterpret_cast<const float4*>(input_mask  + rbase)[tid];
    float tv[4] = {e4.x, e4.y, e4.z, e4.w};
    float mv[4] = {m4.x, m4.y, m4.z, m4.w};

    // ---- local pass ----
    float sumt = 0.f, sumj = 0.f, mf = 0.f, lfill = 0.f;
    #pragma unroll
    for (int j = 0; j < 4; j++) {
        sumt  = fmaf(mv[j], tv[j], sumt);
        sumj  = fmaf(mv[j], (float)j, sumj);
        mf   += mv[j];
        lfill = (mv[j] > 0.5f) ? tv[j] : lfill;
    }
    const float fbase = (float)(tid * 4);
    float ll = fmaf(mu, sumt, -beta * fmaf(fbase, mf, sumj));

    // ---- warp inclusive count scan (single value) ----
    float c = mf;
    #pragma unroll
    for (int off = 1; off < 32; off <<= 1) {
        float u = __shfl_up_sync(FULL, c, off);
        if (lane >= off) c += u;
    }

    // ---- forward-fill via ballot + clz + shfl.idx (no fill scan) ----
    const bool has = mf > 0.f;
    const unsigned bm    = __ballot_sync(FULL, has);
    const unsigned below = bm & ((1u << lane) - 1u);
    const int srcPrev = below ? (31 - __clz((int)below)) : 0;
    const float plWarp = __shfl_sync(FULL, lfill, srcPrev);

    // warp totals
    const float Mw = __shfl_sync(FULL, c, 31);
    const int srcLast = bm ? (31 - __clz((int)bm)) : 0;
    const float wlast = __shfl_sync(FULL, lfill, srcLast);

    // ---- warp reduce loglik ----
    float llr = ll;
    #pragma unroll
    for (int off = 16; off; off >>= 1) llr += __shfl_down_sync(FULL, llr, off);

    __shared__ float wC[NW], wL[NW];    // per-warp count, last-fill
    __shared__ float pC[NW], pL[NW];    // exclusive prefixes (pL seeded with t0)
    __shared__ float rL[NW], rC[NW];    // reduction scratch
    __shared__ float sStat[3];          // Mtot, lastT, ll_sum

    if (lane == 0) {
        wC[wid] = Mw;
        wL[wid] = bm ? wlast : 0.0f;
        rL[wid] = llr;
    }
    __syncthreads();   // sync 1

    // ---- warp 0: cross-warp prefix over 16 entries + block stats ----
    if (wid == 0) {
        float cc = 0.f, wl = 0.f;
        if (lane < NW) { cc = wC[lane]; wl = wL[lane]; }
        const unsigned bm16 = __ballot_sync(FULL, cc > 0.f);
        float sc = cc;
        #pragma unroll
        for (int off = 1; off < 16; off <<= 1) {
            float u = __shfl_up_sync(FULL, sc, off);
            if (lane >= off) sc += u;
        }
        const unsigned b16 = bm16 & ((1u << lane) - 1u);
        const int sp = b16 ? (31 - __clz((int)b16)) : 0;
        const float pf = __shfl_sync(FULL, wl, sp);
        if (lane < NW) {
            pC[lane] = sc - cc;
            pL[lane] = b16 ? pf : t0;
        }
        const float Mtot = __shfl_sync(FULL, sc, 15);
        const int sl = bm16 ? (31 - __clz((int)bm16)) : 0;
        const float lT = __shfl_sync(FULL, wl, sl);
        // sum loglik partials (16 valid lanes)
        float a = (lane < NW) ? rL[lane] : 0.f;
        #pragma unroll
        for (int off = 8; off; off >>= 1) a += __shfl_down_sync(FULL, a, off);
        if (lane == 0) {
            sStat[0] = Mtot;
            sStat[1] = bm16 ? lT : t0;
            sStat[2] = a;
        }
    }
    __syncthreads();   // sync 2

    // ---- per-thread exclusive quantities ----
    const float Kexcl  = pC[wid] + (c - mf);
    const float prev_t = below ? plWarp : pL[wid];

    // ---- compensator contribution (exp gated by fp32 underflow bound) ----
    float contrib = 0.f;
    const float bK = beta * Kexcl;
    if (has && bK < 104.0f) {
        float cw    = expf(-bK);          // e^{-beta*K} folded into coefficient
        const float emb = expf(-beta);
        float prevE = expf(mu * prev_t);
        #pragma unroll
        for (int j = 0; j < 4; j++) {
            if (mv[j] > 0.5f) {
                const float E = expf(mu * tv[j]);
                contrib = fmaf(cw, E - prevE, contrib);
                prevE = E;
                cw *= emb;
            }
        }
    }

    // ---- reduce contrib ----
    #pragma unroll
    for (int off = 16; off; off >>= 1) contrib += __shfl_down_sync(FULL, contrib, off);
    if (lane == 0) rC[wid] = contrib;
    __syncthreads();   // sync 3

    if (tid == 0) {
        float comp = 0.f;
        #pragma unroll
        for (int w = 0; w < NW; w++) comp += rC[w];
        const float Mtot  = sStat[0];
        const float lastT = sStat[1];
        const float llsum = sStat[2];
        const float bM = beta * Mtot;
        if (bM < 104.0f) {
            comp += expf(-bM) * (expf(mu * t1) - expf(mu * lastT));
        }
        out[row] = llsum - comp / mu;
    }
}

extern "C" void kernel_launch(void* const* d_in, const int* in_sizes, int n_in,
                              void* d_out, int out_size)
{
    const float* event_times = (const float*)d_in[0];
    // d_in[1] = spatial_locations : unused by the op
    const float* input_mask  = (const float*)d_in[2];
    const float* t0          = (const float*)d_in[3];
    const float* t1          = (const float*)d_in[4];
    const float* mu_param    = (const float*)d_in[5];
    const float* beta_param  = (const float*)d_in[6];
    float* out = (float*)d_out;

    const int n_rows = out_size;  // 8192
    scpp_kernel<<<n_rows, NT>>>(event_times, input_mask, t0, t1,
                                mu_param, beta_param, out);
}

// round 4
// speedup vs baseline: 1.3279x; 1.3279x over previous
#include <cuda_runtime.h>
#include <math.h>

#define T_LEN 2048
#define NT 256
#define NW 8
#define FULL 0xFFFFFFFFu

__global__ __launch_bounds__(NT, 6)
void scpp_kernel(const float* __restrict__ event_times,
                 const float* __restrict__ input_mask,
                 const float* __restrict__ t0p,
                 const float* __restrict__ t1p,
                 const float* __restrict__ mup,
                 const float* __restrict__ betap,
                 float* __restrict__ out)
{
    const int row  = blockIdx.x;
    const int tid  = threadIdx.x;
    const int lane = tid & 31;
    const int wid  = tid >> 5;

    const float mu   = log1pf(expf(__ldg(mup)));
    const float beta = log1pf(expf(__ldg(betap)));
    const float t0   = __ldg(t0p);
    const float t1   = __ldg(t1p);

    // ---- fully coalesced: thread t owns elems [4t..4t+3] and [1024+4t..1024+4t+3]
    const size_t rbase = (size_t)row * T_LEN;
    const float4* ev = reinterpret_cast<const float4*>(event_times + rbase);
    const float4* mk = reinterpret_cast<const float4*>(input_mask  + rbase);
    const float4 eA = ev[tid],      eB = ev[tid + NT];
    const float4 mA = mk[tid],      mB = mk[tid + NT];
    const float tA[4] = {eA.x, eA.y, eA.z, eA.w};
    const float vA[4] = {mA.x, mA.y, mA.z, mA.w};
    const float tB[4] = {eB.x, eB.y, eB.z, eB.w};
    const float vB[4] = {mB.x, mB.y, mB.z, mB.w};

    // ---- local pass: loglik partials + masked counts per half ----
    const float baseA = (float)(4 * tid);
    const float baseB = (float)(1024 + 4 * tid);
    float sumt = 0.f, sumidx = 0.f;
    int cA = 0, cB = 0;
    #pragma unroll
    for (int j = 0; j < 4; j++) {
        sumt   = fmaf(vA[j], tA[j], sumt);
        sumidx = fmaf(vA[j], baseA + (float)j, sumidx);
        cA += (vA[j] > 0.5f) ? 1 : 0;
        sumt   = fmaf(vB[j], tB[j], sumt);
        sumidx = fmaf(vB[j], baseB + (float)j, sumidx);
        cB += (vB[j] > 0.5f) ? 1 : 0;
    }
    float ll = fmaf(mu, sumt, -beta * sumidx);

    // ---- single packed count scan: hi16 = half A, lo16 = half B ----
    const int pm = (cA << 16) | cB;
    int c = pm;
    #pragma unroll
    for (int off = 1; off < 32; off <<= 1) {
        int u = __shfl_up_sync(FULL, c, off);
        if (lane >= off) c += u;
    }

    // ---- warp reduce loglik while scan result settles ----
    float llr = ll;
    #pragma unroll
    for (int off = 16; off; off >>= 1) llr += __shfl_down_sync(FULL, llr, off);

    __shared__ int   wC[NW], pC[NW];
    __shared__ int   sGrand;
    __shared__ float rL[NW], rS[NW];

    if (lane == 31) wC[wid] = c;
    if (lane == 0)  rL[wid] = llr;
    __syncthreads();   // sync 1

    if (wid == 0 && lane < NW) {
        int cc = wC[lane];
        #pragma unroll
        for (int off = 1; off < NW; off <<= 1) {
            int u = __shfl_up_sync(0xFF, cc, off);
            if (lane >= off) cc += u;
        }
        int ce = __shfl_up_sync(0xFF, cc, 1);
        pC[lane] = (lane == 0) ? 0 : ce;
        if (lane == NW - 1) sGrand = cc;
    }
    __syncthreads();   // sync 2

    // ---- exclusive masked ranks ----
    const int excl  = pC[wid] + c - pm;          // packed
    const int MAtot = sGrand >> 16;
    const int kA0   = excl >> 16;
    const int kB0   = MAtot + (excl & 0xFFFF);

    // ---- S partial: sum over masked events of exp(mu*t - beta*k), gated ----
    float contrib = 0.f;
    if (cA && beta * (float)kA0 < 104.0f) {
        float k = (float)kA0;
        #pragma unroll
        for (int j = 0; j < 4; j++) {
            if (vA[j] > 0.5f) {
                contrib += expf(fmaf(mu, tA[j], -beta * k));
                k += 1.0f;
            }
        }
    }
    if (cB && beta * (float)kB0 < 104.0f) {
        float k = (float)kB0;
        #pragma unroll
        for (int j = 0; j < 4; j++) {
            if (vB[j] > 0.5f) {
                contrib += expf(fmaf(mu, tB[j], -beta * k));
                k += 1.0f;
            }
        }
    }

    #pragma unroll
    for (int off = 16; off; off >>= 1) contrib += __shfl_down_sync(FULL, contrib, off);
    if (lane == 0) rS[wid] = contrib;
    __syncthreads();   // sync 3

    if (tid == 0) {
        float llsum = 0.f, S = 0.f;
        #pragma unroll
        for (int w = 0; w < NW; w++) { llsum += rL[w]; S += rS[w]; }
        const int   Mtot = (sGrand >> 16) + (sGrand & 0xFFFF);
        const float emb  = expf(-beta);
        const float bM   = beta * (float)Mtot;
        float comp = fmaf(1.0f - emb, S, -expf(mu * t0));
        if (bM < 104.0f) comp += expf(fmaf(mu, t1, -bM));
        out[row] = llsum - comp / mu;
    }
}

extern "C" void kernel_launch(void* const* d_in, const int* in_sizes, int n_in,
                              void* d_out, int out_size)
{
    const float* event_times = (const float*)d_in[0];
    // d_in[1] = spatial_locations : unused by the op
    const float* input_mask  = (const float*)d_in[2];
    const float* t0          = (const float*)d_in[3];
    const float* t1          = (const float*)d_in[4];
    const float* mu_param    = (const float*)d_in[5];
    const float* beta_param  = (const float*)d_in[6];
    float* out = (float*)d_out;

    const int n_rows = out_size;  // 8192
    scpp_kernel<<<n_rows, NT>>>(event_times, input_mask, t0, t1,
                                mu_param, beta_param, out);
}